// round 12
// baseline (speedup 1.0000x reference)
#include <cuda_runtime.h>
#include <math.h>

#define NMAX 100000
#define BMAX 256
#define H 64
#define EPS 1e-5f

// ---------------- scratch (no allocations allowed) ----------------
__device__ __align__(16) float  g_h[NMAX * H];     // node features
__device__ __align__(16) float  g_u[NMAX * H];     // h @ Wh + conv_b  (per layer)
__device__ __align__(16) float4 g_stats[NMAX];     // {E[u], Var(u), Cov(u,W0), Cov(u,W1)}
__device__ __align__(16) float  g_agg[NMAX * H];   // scatter accumulator
__device__ float g_deg[NMAX];
__device__ __align__(16) float g_pool[BMAX * H];
__device__ float g_cnt[BMAX];
__device__ float g_wc[3][8];   // per-layer: {E[W0], E[W1], Var(W0), Var(W1), Cov(W0,W1)}

// ---------------- helpers ----------------
__device__ __forceinline__ float warp_sum(float v) {
#pragma unroll
    for (int o = 16; o; o >>= 1) v += __shfl_xor_sync(0xffffffffu, v, o);
    return v;
}

__device__ __forceinline__ float gelu_f(float x) {
    // exact (erf) GELU, matching jax.nn.gelu(approximate=False)
    return 0.5f * x * (1.0f + erff(x * 0.7071067811865476f));
}

__device__ __forceinline__ void red_add_f4(float4* p, float4 v) {
    asm volatile("red.global.add.v4.f32 [%0], {%1, %2, %3, %4};"
                 :: "l"(p), "f"(v.x), "f"(v.y), "f"(v.z), "f"(v.w)
                 : "memory");
}

// ---------------- kernels ----------------
__global__ void k_zero(int N, int B) {
    int i = blockIdx.x * blockDim.x + threadIdx.x;
    int s = gridDim.x * blockDim.x;
    for (int j = i; j < N; j += s) g_deg[j] = 0.f;
    for (int j = i; j < B * H; j += s) g_pool[j] = 0.f;
    for (int j = i; j < B; j += s) g_cnt[j] = 0.f;
}

__global__ void k_deg(const int* __restrict__ ei, int E) {
    int i = blockIdx.x * blockDim.x + threadIdx.x;
    int s = gridDim.x * blockDim.x;
    for (int e = i; e < E; e += s) atomicAdd(&g_deg[ei[E + e]], 1.0f);
}

// node embedding: Linear(2,H)+LN+GELU, Linear(H,H)+LN+GELU
__global__ void __launch_bounds__(256)
k_embed(const float* __restrict__ x,
        const float* __restrict__ w1, const float* __restrict__ b1,
        const float* __restrict__ g1, const float* __restrict__ be1,
        const float* __restrict__ w2, const float* __restrict__ b2,
        const float* __restrict__ g2, const float* __restrict__ be2,
        int N) {
    __shared__ float sW[H * H];
    __shared__ float sA[8][H];
    for (int i = threadIdx.x; i < H * H; i += blockDim.x) sW[i] = w2[i];
    __syncthreads();
    int w = threadIdx.x >> 5, lane = threadIdx.x & 31;
    int n = blockIdx.x * 8 + w;
    if (n >= N) return;
    int j0 = lane, j1 = lane + 32;
    float x0 = x[2 * n], x1 = x[2 * n + 1];
    float p0 = x0 * w1[j0] + x1 * w1[H + j0] + b1[j0];
    float p1 = x0 * w1[j1] + x1 * w1[H + j1] + b1[j1];
    float mu = warp_sum(p0 + p1) * (1.0f / H);
    float d0 = p0 - mu, d1 = p1 - mu;
    float var = warp_sum(d0 * d0 + d1 * d1) * (1.0f / H);
    float rs = rsqrtf(var + EPS);
    sA[w][j0] = gelu_f(d0 * rs * g1[j0] + be1[j0]);
    sA[w][j1] = gelu_f(d1 * rs * g1[j1] + be1[j1]);
    __syncwarp();
    float q0 = b2[j0], q1 = b2[j1];
#pragma unroll 8
    for (int k = 0; k < H; k++) {
        float hv = sA[w][k];
        q0 += hv * sW[k * H + j0];
        q1 += hv * sW[k * H + j1];
    }
    mu = warp_sum(q0 + q1) * (1.0f / H);
    d0 = q0 - mu; d1 = q1 - mu;
    var = warp_sum(d0 * d0 + d1 * d1) * (1.0f / H);
    rs = rsqrtf(var + EPS);
    g_h[n * H + j0] = gelu_f(d0 * rs * g2[j0] + be2[j0]);
    g_h[n * H + j1] = gelu_f(d1 * rs * g2[j1] + be2[j1]);
}

// weight-only constants for the closed-form edge LayerNorm, all 3 layers at once.
// blockDim = 96 (3 warps); warp l handles layer l. Centered moments (no cancellation).
__global__ void k_wconst(const float* __restrict__ conv_w) {
    int l = threadIdx.x >> 5, lane = threadIdx.x & 31;
    const float* W0 = conv_w + l * 66 * H + 64 * H;
    const float* W1 = W0 + H;
    float a0 = W0[lane], a1 = W0[lane + 32];
    float b0 = W1[lane], b1 = W1[lane + 32];
    float m0 = warp_sum(a0 + a1) * (1.0f / H);
    float m1 = warp_sum(b0 + b1) * (1.0f / H);
    float da0 = a0 - m0, da1 = a1 - m0;
    float db0 = b0 - m1, db1 = b1 - m1;
    float v0  = warp_sum(da0 * da0 + da1 * da1) * (1.0f / H);
    float v1  = warp_sum(db0 * db0 + db1 * db1) * (1.0f / H);
    float c01 = warp_sum(da0 * db0 + da1 * db1) * (1.0f / H);
    if (lane == 0) {
        g_wc[l][0] = m0; g_wc[l][1] = m1;
        g_wc[l][2] = v0; g_wc[l][3] = v1; g_wc[l][4] = c01;
    }
}

// per node: u = h @ Wh + conv_b, centered per-node LN stats, zero agg
__global__ void __launch_bounds__(256)
k_prep(const float* __restrict__ conv_w,
       const float* __restrict__ conv_b, int l, int N) {
    __shared__ float sW[H * H];
    __shared__ float sH[8][H];
    const float* Wh = conv_w + l * 66 * H;
    for (int i = threadIdx.x; i < H * H; i += blockDim.x) sW[i] = Wh[i];
    __syncthreads();
    int w = threadIdx.x >> 5, lane = threadIdx.x & 31;
    int n = blockIdx.x * 8 + w;
    if (n >= N) return;
    int j0 = lane, j1 = lane + 32;
    sH[w][j0] = g_h[n * H + j0];
    sH[w][j1] = g_h[n * H + j1];
    __syncwarp();
    float u0 = conv_b[l * H + j0], u1 = conv_b[l * H + j1];
#pragma unroll 8
    for (int k = 0; k < H; k++) {
        float hv = sH[w][k];
        u0 += hv * sW[k * H + j0];
        u1 += hv * sW[k * H + j1];
    }
    g_u[n * H + j0] = u0;
    g_u[n * H + j1] = u1;
    g_agg[n * H + j0] = 0.f;
    g_agg[n * H + j1] = 0.f;
    const float* W0 = conv_w + l * 66 * H + 64 * H;
    const float* W1 = W0 + H;
    float m0 = g_wc[l][0], m1 = g_wc[l][1];
    float mu_u = warp_sum(u0 + u1) * (1.0f / H);
    float d0 = u0 - mu_u, d1 = u1 - mu_u;
    float var_u = warp_sum(d0 * d0 + d1 * d1) * (1.0f / H);
    // centered covariances: Cov(u, W) = E[(u-mu_u)(W-mW)]
    float cu0 = warp_sum(d0 * (W0[j0] - m0) + d1 * (W0[j1] - m0)) * (1.0f / H);
    float cu1 = warp_sum(d0 * (W1[j0] - m1) + d1 * (W1[j1] - m1)) * (1.0f / H);
    if (lane == 0)
        g_stats[n] = make_float4(mu_u, var_u, cu0, cu1);
}

// per edge: closed-form LN + GELU + vector scatter-add. 16 threads / edge (float4 lanes).
// 2-edge manual unroll; LN affine folded into per-edge {gm*rs, gb - mu*gm*rs}.
// Launched as exactly one wave (148 SMs x 8 blocks).
__global__ void __launch_bounds__(256)
k_edge(const int* __restrict__ ei, const float* __restrict__ ea,
       const float* __restrict__ conv_w,
       const float* __restrict__ mg, const float* __restrict__ mb,
       int l, int E) {
    int sub = threadIdx.x & 15;
    int group = (blockIdx.x * blockDim.x + threadIdx.x) >> 4;
    int ngroups = (gridDim.x * blockDim.x) >> 4;
    int ngroups2 = ngroups * 2;
    const float* W0 = conv_w + l * 66 * H + 64 * H;
    const float* W1 = W0 + H;
    const int* eid = ei + E;   // dst half
    float4 w0 = ((const float4*)W0)[sub];
    float4 w1 = ((const float4*)W1)[sub];
    float4 gm = ((const float4*)(mg + l * H))[sub];
    float4 gb = ((const float4*)(mb + l * H))[sub];
    float m0 = g_wc[l][0], m1 = g_wc[l][1];
    float v0 = g_wc[l][2], v1 = g_wc[l][3], c01 = g_wc[l][4];
    const float4* U4 = (const float4*)g_u;
    const float2* EA2 = (const float2*)ea;
    float4* A4 = (float4*)g_agg;

    int e = group;
    // main 2-edge unrolled loop
    for (; e + ngroups < E; e += ngroups2) {
        int ea_ = e, eb_ = e + ngroups;
        int srcA = __ldg(&ei[ea_]);
        int srcB = __ldg(&ei[eb_]);
        int dstA = __ldg(&eid[ea_]);
        int dstB = __ldg(&eid[eb_]);
        float2 evA = __ldg(&EA2[ea_]);
        float2 evB = __ldg(&EA2[eb_]);
        float4 sA = g_stats[srcA];
        float4 sB = g_stats[srcB];
        float4 uA = U4[srcA * 16 + sub];
        float4 uB = U4[srcB * 16 + sub];

        {
            float a0 = evA.x, a1 = evA.y;
            float mu = sA.x + a0 * m0 + a1 * m1;
            float var = sA.y + a0 * a0 * v0 + a1 * a1 * v1
                      + 2.f * (a0 * sA.z + a1 * sA.w + a0 * a1 * c01);
            float rs = rsqrtf(fmaxf(var, 0.f) + EPS);
            // fold affine: z = gelu(pre * (gm*rs) + (gb - mu*gm*rs))
            float4 gr, sh;
            gr.x = gm.x * rs; sh.x = fmaf(-mu, gr.x, gb.x);
            gr.y = gm.y * rs; sh.y = fmaf(-mu, gr.y, gb.y);
            gr.z = gm.z * rs; sh.z = fmaf(-mu, gr.z, gb.z);
            gr.w = gm.w * rs; sh.w = fmaf(-mu, gr.w, gb.w);
            float4 z;
            z.x = gelu_f(fmaf(fmaf(a1, w1.x, fmaf(a0, w0.x, uA.x)), gr.x, sh.x));
            z.y = gelu_f(fmaf(fmaf(a1, w1.y, fmaf(a0, w0.y, uA.y)), gr.y, sh.y));
            z.z = gelu_f(fmaf(fmaf(a1, w1.z, fmaf(a0, w0.z, uA.z)), gr.z, sh.z));
            z.w = gelu_f(fmaf(fmaf(a1, w1.w, fmaf(a0, w0.w, uA.w)), gr.w, sh.w));
            red_add_f4(&A4[dstA * 16 + sub], z);
        }
        {
            float b0 = evB.x, b1 = evB.y;
            float mu = sB.x + b0 * m0 + b1 * m1;
            float var = sB.y + b0 * b0 * v0 + b1 * b1 * v1
                      + 2.f * (b0 * sB.z + b1 * sB.w + b0 * b1 * c01);
            float rs = rsqrtf(fmaxf(var, 0.f) + EPS);
            float4 gr, sh;
            gr.x = gm.x * rs; sh.x = fmaf(-mu, gr.x, gb.x);
            gr.y = gm.y * rs; sh.y = fmaf(-mu, gr.y, gb.y);
            gr.z = gm.z * rs; sh.z = fmaf(-mu, gr.z, gb.z);
            gr.w = gm.w * rs; sh.w = fmaf(-mu, gr.w, gb.w);
            float4 z;
            z.x = gelu_f(fmaf(fmaf(b1, w1.x, fmaf(b0, w0.x, uB.x)), gr.x, sh.x));
            z.y = gelu_f(fmaf(fmaf(b1, w1.y, fmaf(b0, w0.y, uB.y)), gr.y, sh.y));
            z.z = gelu_f(fmaf(fmaf(b1, w1.z, fmaf(b0, w0.z, uB.z)), gr.z, sh.z));
            z.w = gelu_f(fmaf(fmaf(b1, w1.w, fmaf(b0, w0.w, uB.w)), gr.w, sh.w));
            red_add_f4(&A4[dstB * 16 + sub], z);
        }
    }
    // tail
    for (; e < E; e += ngroups) {
        int src = __ldg(&ei[e]);
        int dst = __ldg(&eid[e]);
        float2 eav = __ldg(&EA2[e]);
        float e0 = eav.x, e1 = eav.y;
        float4 s = g_stats[src];
        float mu = s.x + e0 * m0 + e1 * m1;
        float var = s.y + e0 * e0 * v0 + e1 * e1 * v1
                  + 2.f * (e0 * s.z + e1 * s.w + e0 * e1 * c01);
        float rs = rsqrtf(fmaxf(var, 0.f) + EPS);
        float4 u = U4[src * 16 + sub];
        float4 gr, sh;
        gr.x = gm.x * rs; sh.x = fmaf(-mu, gr.x, gb.x);
        gr.y = gm.y * rs; sh.y = fmaf(-mu, gr.y, gb.y);
        gr.z = gm.z * rs; sh.z = fmaf(-mu, gr.z, gb.z);
        gr.w = gm.w * rs; sh.w = fmaf(-mu, gr.w, gb.w);
        float4 z;
        z.x = gelu_f(fmaf(fmaf(e1, w1.x, fmaf(e0, w0.x, u.x)), gr.x, sh.x));
        z.y = gelu_f(fmaf(fmaf(e1, w1.y, fmaf(e0, w0.y, u.y)), gr.y, sh.y));
        z.z = gelu_f(fmaf(fmaf(e1, w1.z, fmaf(e0, w0.z, u.z)), gr.z, sh.z));
        z.w = gelu_f(fmaf(fmaf(e1, w1.w, fmaf(e0, w0.w, u.w)), gr.w, sh.w));
        red_add_f4(&A4[dst * 16 + sub], z);
    }
}

// per node: conv_out = LN(agg/deg + h); h += LN(conv_out); optional pooling on last layer
__global__ void __launch_bounds__(256)
k_update(const float* __restrict__ ng, const float* __restrict__ nb,
         const float* __restrict__ og, const float* __restrict__ ob,
         const int* __restrict__ batch, int l, int N, int last) {
    int w = threadIdx.x >> 5, lane = threadIdx.x & 31;
    int n = blockIdx.x * 8 + w;
    if (n >= N) return;
    int j0 = lane, j1 = lane + 32;
    float inv = 1.0f / fmaxf(g_deg[n], 1.0f);
    float h0 = g_h[n * H + j0], h1 = g_h[n * H + j1];
    float a0 = g_agg[n * H + j0] * inv + h0;
    float a1 = g_agg[n * H + j1] * inv + h1;
    float mu = warp_sum(a0 + a1) * (1.0f / H);
    float d0 = a0 - mu, d1 = a1 - mu;
    float var = warp_sum(d0 * d0 + d1 * d1) * (1.0f / H);
    float rs = rsqrtf(var + EPS);
    float co0 = d0 * rs * ng[l * H + j0] + nb[l * H + j0];
    float co1 = d1 * rs * ng[l * H + j1] + nb[l * H + j1];
    mu = warp_sum(co0 + co1) * (1.0f / H);
    d0 = co0 - mu; d1 = co1 - mu;
    var = warp_sum(d0 * d0 + d1 * d1) * (1.0f / H);
    rs = rsqrtf(var + EPS);
    h0 += d0 * rs * og[l * H + j0] + ob[l * H + j0];
    h1 += d1 * rs * og[l * H + j1] + ob[l * H + j1];
    g_h[n * H + j0] = h0;
    g_h[n * H + j1] = h1;
    if (last) {
        int b = batch[n];
        atomicAdd(&g_pool[b * H + j0], h0);
        atomicAdd(&g_pool[b * H + j1], h1);
        if (lane == 0) atomicAdd(&g_cnt[b], 1.0f);
    }
}

// head MLP: Linear(H,H)+LN+ReLU, Linear(H,H/2)+LN+ReLU, Linear(H/2,1)
__global__ void __launch_bounds__(256)
k_head(const float* __restrict__ w1, const float* __restrict__ b1,
       const float* __restrict__ g1, const float* __restrict__ be1,
       const float* __restrict__ w2, const float* __restrict__ b2,
       const float* __restrict__ g2, const float* __restrict__ be2,
       const float* __restrict__ w3, const float* __restrict__ b3,
       float* __restrict__ out, int B) {
    __shared__ float sG[8][H];
    __shared__ float sR[8][H];
    int w = threadIdx.x >> 5, lane = threadIdx.x & 31;
    int b = blockIdx.x * 8 + w;
    if (b >= B) return;
    float inv = 1.0f / fmaxf(g_cnt[b], 1.0f);
    int j0 = lane, j1 = lane + 32;
    sG[w][j0] = g_pool[b * H + j0] * inv;
    sG[w][j1] = g_pool[b * H + j1] * inv;
    __syncwarp();
    float q0 = b1[j0], q1 = b1[j1];
#pragma unroll 8
    for (int k = 0; k < H; k++) {
        float v = sG[w][k];
        q0 += v * w1[k * H + j0];
        q1 += v * w1[k * H + j1];
    }
    float mu = warp_sum(q0 + q1) * (1.0f / H);
    float d0 = q0 - mu, d1 = q1 - mu;
    float var = warp_sum(d0 * d0 + d1 * d1) * (1.0f / H);
    float rs = rsqrtf(var + EPS);
    sR[w][j0] = fmaxf(d0 * rs * g1[j0] + be1[j0], 0.f);
    sR[w][j1] = fmaxf(d1 * rs * g1[j1] + be1[j1], 0.f);
    __syncwarp();
    float q = b2[lane];
#pragma unroll 8
    for (int k = 0; k < H; k++) q += sR[w][k] * w2[k * 32 + lane];
    mu = warp_sum(q) * (1.0f / 32.0f);
    float d = q - mu;
    var = warp_sum(d * d) * (1.0f / 32.0f);
    rs = rsqrtf(var + EPS);
    float r = fmaxf(d * rs * g2[lane] + be2[lane], 0.f);
    float v = warp_sum(r * w3[lane]);
    if (lane == 0) out[b] = v + b3[0];
}

// ---------------- launch ----------------
extern "C" void kernel_launch(void* const* d_in, const int* in_sizes, int n_in,
                              void* d_out, int out_size) {
    const float* x       = (const float*)d_in[0];
    const float* eattr   = (const float*)d_in[1];
    const float* ne_w1   = (const float*)d_in[2];
    const float* ne_b1   = (const float*)d_in[3];
    const float* ne_g1   = (const float*)d_in[4];
    const float* ne_be1  = (const float*)d_in[5];
    const float* ne_w2   = (const float*)d_in[6];
    const float* ne_b2   = (const float*)d_in[7];
    const float* ne_g2   = (const float*)d_in[8];
    const float* ne_be2  = (const float*)d_in[9];
    const float* conv_w  = (const float*)d_in[10];
    const float* conv_b  = (const float*)d_in[11];
    const float* conv_mg = (const float*)d_in[12];
    const float* conv_mb = (const float*)d_in[13];
    const float* conv_ng = (const float*)d_in[14];
    const float* conv_nb = (const float*)d_in[15];
    const float* out_ng  = (const float*)d_in[16];
    const float* out_nb  = (const float*)d_in[17];
    const float* m_w1    = (const float*)d_in[18];
    const float* m_b1    = (const float*)d_in[19];
    const float* m_g1    = (const float*)d_in[20];
    const float* m_be1   = (const float*)d_in[21];
    const float* m_w2    = (const float*)d_in[22];
    const float* m_b2    = (const float*)d_in[23];
    const float* m_g2    = (const float*)d_in[24];
    const float* m_be2   = (const float*)d_in[25];
    const float* m_w3    = (const float*)d_in[26];
    const float* m_b3    = (const float*)d_in[27];
    const int*   ei      = (const int*)d_in[28];
    const int*   batch   = (const int*)d_in[29];

    int N = in_sizes[0] / 2;
    int E = in_sizes[1] / 2;
    int B = out_size;

    int nblk = (N + 7) / 8;
    const int EDGE_BLOCKS = 148 * 8;   // exactly one wave at 8 blocks/SM

    int zero_work = N + B * H + B;
    int zblk = (zero_work + 255) / 256;
    if (zblk > 1184) zblk = 1184;

    k_zero<<<zblk, 256>>>(N, B);
    k_deg<<<EDGE_BLOCKS, 256>>>(ei, E);
    k_embed<<<nblk, 256>>>(x, ne_w1, ne_b1, ne_g1, ne_be1,
                           ne_w2, ne_b2, ne_g2, ne_be2, N);
    k_wconst<<<1, 96>>>(conv_w);
    for (int l = 0; l < 3; l++) {
        k_prep<<<nblk, 256>>>(conv_w, conv_b, l, N);
        k_edge<<<EDGE_BLOCKS, 256>>>(ei, eattr, conv_w, conv_mg, conv_mb, l, E);
        k_update<<<nblk, 256>>>(conv_ng, conv_nb, out_ng, out_nb,
                                batch, l, N, l == 2 ? 1 : 0);
    }
    k_head<<<(B + 7) / 8, 256>>>(m_w1, m_b1, m_g1, m_be1,
                                 m_w2, m_b2, m_g2, m_be2,
                                 m_w3, m_b3, (float*)d_out, B);
}

// round 13
// speedup vs baseline: 1.0427x; 1.0427x over previous
#include <cuda_runtime.h>
#include <math.h>

#define NMAX 100000
#define BMAX 256
#define H 64
#define EPS 1e-5f

typedef unsigned long long ull;

// ---------------- scratch (no allocations allowed) ----------------
__device__ __align__(16) float  g_h[NMAX * H];     // node features
__device__ __align__(16) float  g_u[NMAX * H];     // h @ Wh + conv_b  (per layer)
__device__ __align__(16) float4 g_stats[NMAX];     // {E[u], Var(u), 2Cov(u,W0), 2Cov(u,W1)}
__device__ __align__(16) float  g_agg[NMAX * H];   // scatter accumulator
__device__ float g_deg[NMAX];
__device__ __align__(16) float g_pool[BMAX * H];
__device__ float g_cnt[BMAX];
__device__ float g_wc[3][8];   // per-layer: {E[W0], E[W1], Var(W0), Var(W1), 2Cov(W0,W1)}

// ---------------- helpers ----------------
__device__ __forceinline__ float warp_sum(float v) {
#pragma unroll
    for (int o = 16; o; o >>= 1) v += __shfl_xor_sync(0xffffffffu, v, o);
    return v;
}

__device__ __forceinline__ float gelu_f(float x) {
    // exact (erf) GELU, matching jax.nn.gelu(approximate=False)
    return 0.5f * x * (1.0f + erff(x * 0.7071067811865476f));
}

__device__ __forceinline__ void red_add_f4(float4* p, float4 v) {
    asm volatile("red.global.add.v4.f32 [%0], {%1, %2, %3, %4};"
                 :: "l"(p), "f"(v.x), "f"(v.y), "f"(v.z), "f"(v.w)
                 : "memory");
}

// ---- packed f32x2 (Blackwell): each half rounds exactly like scalar fma.rn ----
__device__ __forceinline__ ull d_pack(float lo, float hi) {
    ull d;
    asm("mov.b64 %0, {%1, %2};" : "=l"(d) : "f"(lo), "f"(hi));
    return d;
}
__device__ __forceinline__ void d_unpack(ull v, float& lo, float& hi) {
    asm("mov.b64 {%0, %1}, %2;" : "=f"(lo), "=f"(hi) : "l"(v));
}
__device__ __forceinline__ ull d_fma2(ull a, ull b, ull c) {
    ull d;
    asm("fma.rn.f32x2 %0, %1, %2, %3;" : "=l"(d) : "l"(a), "l"(b), "l"(c));
    return d;
}
__device__ __forceinline__ ull d_mul2(ull a, ull b) {
    ull d;
    asm("mul.rn.f32x2 %0, %1, %2;" : "=l"(d) : "l"(a), "l"(b));
    return d;
}

// ---------------- kernels ----------------
__global__ void k_zero(int N, int B) {
    int i = blockIdx.x * blockDim.x + threadIdx.x;
    int s = gridDim.x * blockDim.x;
    for (int j = i; j < N; j += s) g_deg[j] = 0.f;
    for (int j = i; j < B * H; j += s) g_pool[j] = 0.f;
    for (int j = i; j < B; j += s) g_cnt[j] = 0.f;
}

__global__ void k_deg(const int* __restrict__ ei, int E) {
    int i = blockIdx.x * blockDim.x + threadIdx.x;
    int s = gridDim.x * blockDim.x;
    for (int e = i; e < E; e += s) atomicAdd(&g_deg[ei[E + e]], 1.0f);
}

// node embedding: Linear(2,H)+LN+GELU, Linear(H,H)+LN+GELU
__global__ void __launch_bounds__(256)
k_embed(const float* __restrict__ x,
        const float* __restrict__ w1, const float* __restrict__ b1,
        const float* __restrict__ g1, const float* __restrict__ be1,
        const float* __restrict__ w2, const float* __restrict__ b2,
        const float* __restrict__ g2, const float* __restrict__ be2,
        int N) {
    __shared__ float sW[H * H];
    __shared__ float sA[8][H];
    for (int i = threadIdx.x; i < H * H; i += blockDim.x) sW[i] = w2[i];
    __syncthreads();
    int w = threadIdx.x >> 5, lane = threadIdx.x & 31;
    int n = blockIdx.x * 8 + w;
    if (n >= N) return;
    int j0 = lane, j1 = lane + 32;
    float x0 = x[2 * n], x1 = x[2 * n + 1];
    float p0 = x0 * w1[j0] + x1 * w1[H + j0] + b1[j0];
    float p1 = x0 * w1[j1] + x1 * w1[H + j1] + b1[j1];
    float mu = warp_sum(p0 + p1) * (1.0f / H);
    float d0 = p0 - mu, d1 = p1 - mu;
    float var = warp_sum(d0 * d0 + d1 * d1) * (1.0f / H);
    float rs = rsqrtf(var + EPS);
    sA[w][j0] = gelu_f(d0 * rs * g1[j0] + be1[j0]);
    sA[w][j1] = gelu_f(d1 * rs * g1[j1] + be1[j1]);
    __syncwarp();
    float q0 = b2[j0], q1 = b2[j1];
#pragma unroll 8
    for (int k = 0; k < H; k++) {
        float hv = sA[w][k];
        q0 += hv * sW[k * H + j0];
        q1 += hv * sW[k * H + j1];
    }
    mu = warp_sum(q0 + q1) * (1.0f / H);
    d0 = q0 - mu; d1 = q1 - mu;
    var = warp_sum(d0 * d0 + d1 * d1) * (1.0f / H);
    rs = rsqrtf(var + EPS);
    g_h[n * H + j0] = gelu_f(d0 * rs * g2[j0] + be2[j0]);
    g_h[n * H + j1] = gelu_f(d1 * rs * g2[j1] + be2[j1]);
}

// weight-only constants for the closed-form edge LayerNorm, all 3 layers at once.
// blockDim = 96 (3 warps); warp l handles layer l. Centered moments.
// Cross-covariance stored pre-doubled.
__global__ void k_wconst(const float* __restrict__ conv_w) {
    int l = threadIdx.x >> 5, lane = threadIdx.x & 31;
    const float* W0 = conv_w + l * 66 * H + 64 * H;
    const float* W1 = W0 + H;
    float a0 = W0[lane], a1 = W0[lane + 32];
    float b0 = W1[lane], b1 = W1[lane + 32];
    float m0 = warp_sum(a0 + a1) * (1.0f / H);
    float m1 = warp_sum(b0 + b1) * (1.0f / H);
    float da0 = a0 - m0, da1 = a1 - m0;
    float db0 = b0 - m1, db1 = b1 - m1;
    float v0  = warp_sum(da0 * da0 + da1 * da1) * (1.0f / H);
    float v1  = warp_sum(db0 * db0 + db1 * db1) * (1.0f / H);
    float c01 = warp_sum(da0 * db0 + da1 * db1) * (2.0f / H);   // 2*Cov(W0,W1)
    if (lane == 0) {
        g_wc[l][0] = m0; g_wc[l][1] = m1;
        g_wc[l][2] = v0; g_wc[l][3] = v1; g_wc[l][4] = c01;
    }
}

// per node: u = h @ Wh + conv_b, centered per-node LN stats (covs pre-doubled), zero agg
__global__ void __launch_bounds__(256)
k_prep(const float* __restrict__ conv_w,
       const float* __restrict__ conv_b, int l, int N) {
    __shared__ float sW[H * H];
    __shared__ float sH[8][H];
    const float* Wh = conv_w + l * 66 * H;
    for (int i = threadIdx.x; i < H * H; i += blockDim.x) sW[i] = Wh[i];
    __syncthreads();
    int w = threadIdx.x >> 5, lane = threadIdx.x & 31;
    int n = blockIdx.x * 8 + w;
    if (n >= N) return;
    int j0 = lane, j1 = lane + 32;
    sH[w][j0] = g_h[n * H + j0];
    sH[w][j1] = g_h[n * H + j1];
    __syncwarp();
    float u0 = conv_b[l * H + j0], u1 = conv_b[l * H + j1];
#pragma unroll 8
    for (int k = 0; k < H; k++) {
        float hv = sH[w][k];
        u0 += hv * sW[k * H + j0];
        u1 += hv * sW[k * H + j1];
    }
    g_u[n * H + j0] = u0;
    g_u[n * H + j1] = u1;
    g_agg[n * H + j0] = 0.f;
    g_agg[n * H + j1] = 0.f;
    const float* W0 = conv_w + l * 66 * H + 64 * H;
    const float* W1 = W0 + H;
    float m0 = g_wc[l][0], m1 = g_wc[l][1];
    float mu_u = warp_sum(u0 + u1) * (1.0f / H);
    float d0 = u0 - mu_u, d1 = u1 - mu_u;
    float var_u = warp_sum(d0 * d0 + d1 * d1) * (1.0f / H);
    // pre-doubled centered covariances: 2*Cov(u, W)
    float cu0 = warp_sum(d0 * (W0[j0] - m0) + d1 * (W0[j1] - m0)) * (2.0f / H);
    float cu1 = warp_sum(d0 * (W1[j0] - m1) + d1 * (W1[j1] - m1)) * (2.0f / H);
    if (lane == 0)
        g_stats[n] = make_float4(mu_u, var_u, cu0, cu1);
}

// one edge's math: closed-form LN (stats pre-loaded), f32x2 packed linear ops, GELU, RED
__device__ __forceinline__ void edge_body(
    float4 s, ulonglong2 uv, float e0, float e1, int dst, int sub,
    float m0, float m1, float v0, float v1, float c01,
    ull w0lo, ull w0hi, ull w1lo, ull w1hi,
    ull gmlo, ull gmhi, ull gblo, ull gbhi,
    float4* A4)
{
    float mu = fmaf(e1, m1, fmaf(e0, m0, s.x));
    float var = fmaf(e0, fmaf(e0, v0, s.z), s.y);
    var = fmaf(e1, fmaf(e1, v1, s.w), var);
    var = fmaf(e0 * e1, c01, var);
    float rs = rsqrtf(fmaxf(var, 0.f) + EPS);
    ull e0p = d_pack(e0, e0), e1p = d_pack(e1, e1);
    ull rsp = d_pack(rs, rs), nmup = d_pack(-mu, -mu);
    ull slo = d_fma2(e1p, w1lo, d_fma2(e0p, w0lo, uv.x));
    ull shi = d_fma2(e1p, w1hi, d_fma2(e0p, w0hi, uv.y));
    ull grlo = d_mul2(gmlo, rsp), grhi = d_mul2(gmhi, rsp);
    ull shlo = d_fma2(nmup, grlo, gblo), shhi = d_fma2(nmup, grhi, gbhi);
    ull xlo = d_fma2(slo, grlo, shlo), xhi = d_fma2(shi, grhi, shhi);
    float a, b;
    float4 z;
    d_unpack(xlo, a, b); z.x = gelu_f(a); z.y = gelu_f(b);
    d_unpack(xhi, a, b); z.z = gelu_f(a); z.w = gelu_f(b);
    red_add_f4(&A4[dst * 16 + sub], z);
}

// per edge: 16 threads / edge (float4 lanes), 2-edge unroll (front-batched loads).
__global__ void __launch_bounds__(256)
k_edge(const int* __restrict__ ei, const float* __restrict__ ea,
       const float* __restrict__ conv_w,
       const float* __restrict__ mg, const float* __restrict__ mb,
       int l, int E) {
    int sub = threadIdx.x & 15;
    int group = (blockIdx.x * blockDim.x + threadIdx.x) >> 4;
    int ngroups = (gridDim.x * blockDim.x) >> 4;
    int ngroups2 = ngroups * 2;
    const float* W0 = conv_w + l * 66 * H + 64 * H;
    const float* W1 = W0 + H;
    const int* eid = ei + E;   // dst half
    float4 w0f = ((const float4*)W0)[sub];
    float4 w1f = ((const float4*)W1)[sub];
    float4 gmf = ((const float4*)(mg + l * H))[sub];
    float4 gbf = ((const float4*)(mb + l * H))[sub];
    ull w0lo = d_pack(w0f.x, w0f.y), w0hi = d_pack(w0f.z, w0f.w);
    ull w1lo = d_pack(w1f.x, w1f.y), w1hi = d_pack(w1f.z, w1f.w);
    ull gmlo = d_pack(gmf.x, gmf.y), gmhi = d_pack(gmf.z, gmf.w);
    ull gblo = d_pack(gbf.x, gbf.y), gbhi = d_pack(gbf.z, gbf.w);
    float m0 = g_wc[l][0], m1 = g_wc[l][1];
    float v0 = g_wc[l][2], v1 = g_wc[l][3], c01 = g_wc[l][4];
    const ulonglong2* U8 = (const ulonglong2*)g_u;
    const float2* EA2 = (const float2*)ea;
    float4* A4 = (float4*)g_agg;

    int e = group;
    for (; e + ngroups < E; e += ngroups2) {
        int ea_ = e, eb_ = e + ngroups;
        int srcA = __ldg(&ei[ea_]);
        int srcB = __ldg(&ei[eb_]);
        int dstA = __ldg(&eid[ea_]);
        int dstB = __ldg(&eid[eb_]);
        float2 evA = __ldg(&EA2[ea_]);
        float2 evB = __ldg(&EA2[eb_]);
        float4 sA = __ldg(&g_stats[srcA]);
        float4 sB = __ldg(&g_stats[srcB]);
        ulonglong2 uvA = __ldg(&U8[srcA * 16 + sub]);
        ulonglong2 uvB = __ldg(&U8[srcB * 16 + sub]);

        edge_body(sA, uvA, evA.x, evA.y, dstA, sub, m0, m1, v0, v1, c01,
                  w0lo, w0hi, w1lo, w1hi, gmlo, gmhi, gblo, gbhi, A4);
        edge_body(sB, uvB, evB.x, evB.y, dstB, sub, m0, m1, v0, v1, c01,
                  w0lo, w0hi, w1lo, w1hi, gmlo, gmhi, gblo, gbhi, A4);
    }
    for (; e < E; e += ngroups) {
        int src = __ldg(&ei[e]);
        int dst = __ldg(&eid[e]);
        float2 eav = __ldg(&EA2[e]);
        float4 s = __ldg(&g_stats[src]);
        ulonglong2 uv = __ldg(&U8[src * 16 + sub]);
        edge_body(s, uv, eav.x, eav.y, dst, sub, m0, m1, v0, v1, c01,
                  w0lo, w0hi, w1lo, w1hi, gmlo, gmhi, gblo, gbhi, A4);
    }
}

// per node: conv_out = LN(agg/deg + h); h += LN(conv_out); optional pooling on last layer
__global__ void __launch_bounds__(256)
k_update(const float* __restrict__ ng, const float* __restrict__ nb,
         const float* __restrict__ og, const float* __restrict__ ob,
         const int* __restrict__ batch, int l, int N, int last) {
    int w = threadIdx.x >> 5, lane = threadIdx.x & 31;
    int n = blockIdx.x * 8 + w;
    if (n >= N) return;
    int j0 = lane, j1 = lane + 32;
    float inv = 1.0f / fmaxf(g_deg[n], 1.0f);
    float h0 = g_h[n * H + j0], h1 = g_h[n * H + j1];
    float a0 = g_agg[n * H + j0] * inv + h0;
    float a1 = g_agg[n * H + j1] * inv + h1;
    float mu = warp_sum(a0 + a1) * (1.0f / H);
    float d0 = a0 - mu, d1 = a1 - mu;
    float var = warp_sum(d0 * d0 + d1 * d1) * (1.0f / H);
    float rs = rsqrtf(var + EPS);
    float co0 = d0 * rs * ng[l * H + j0] + nb[l * H + j0];
    float co1 = d1 * rs * ng[l * H + j1] + nb[l * H + j1];
    mu = warp_sum(co0 + co1) * (1.0f / H);
    d0 = co0 - mu; d1 = co1 - mu;
    var = warp_sum(d0 * d0 + d1 * d1) * (1.0f / H);
    rs = rsqrtf(var + EPS);
    h0 += d0 * rs * og[l * H + j0] + ob[l * H + j0];
    h1 += d1 * rs * og[l * H + j1] + ob[l * H + j1];
    g_h[n * H + j0] = h0;
    g_h[n * H + j1] = h1;
    if (last) {
        int b = batch[n];
        atomicAdd(&g_pool[b * H + j0], h0);
        atomicAdd(&g_pool[b * H + j1], h1);
        if (lane == 0) atomicAdd(&g_cnt[b], 1.0f);
    }
}

// head MLP: Linear(H,H)+LN+ReLU, Linear(H,H/2)+LN+ReLU, Linear(H/2,1)
__global__ void __launch_bounds__(256)
k_head(const float* __restrict__ w1, const float* __restrict__ b1,
       const float* __restrict__ g1, const float* __restrict__ be1,
       const float* __restrict__ w2, const float* __restrict__ b2,
       const float* __restrict__ g2, const float* __restrict__ be2,
       const float* __restrict__ w3, const float* __restrict__ b3,
       float* __restrict__ out, int B) {
    __shared__ float sG[8][H];
    __shared__ float sR[8][H];
    int w = threadIdx.x >> 5, lane = threadIdx.x & 31;
    int b = blockIdx.x * 8 + w;
    if (b >= B) return;
    float inv = 1.0f / fmaxf(g_cnt[b], 1.0f);
    int j0 = lane, j1 = lane + 32;
    sG[w][j0] = g_pool[b * H + j0] * inv;
    sG[w][j1] = g_pool[b * H + j1] * inv;
    __syncwarp();
    float q0 = b1[j0], q1 = b1[j1];
#pragma unroll 8
    for (int k = 0; k < H; k++) {
        float v = sG[w][k];
        q0 += v * w1[k * H + j0];
        q1 += v * w1[k * H + j1];
    }
    float mu = warp_sum(q0 + q1) * (1.0f / H);
    float d0 = q0 - mu, d1 = q1 - mu;
    float var = warp_sum(d0 * d0 + d1 * d1) * (1.0f / H);
    float rs = rsqrtf(var + EPS);
    sR[w][j0] = fmaxf(d0 * rs * g1[j0] + be1[j0], 0.f);
    sR[w][j1] = fmaxf(d1 * rs * g1[j1] + be1[j1], 0.f);
    __syncwarp();
    float q = b2[lane];
#pragma unroll 8
    for (int k = 0; k < H; k++) q += sR[w][k] * w2[k * 32 + lane];
    mu = warp_sum(q) * (1.0f / 32.0f);
    float d = q - mu;
    var = warp_sum(d * d) * (1.0f / 32.0f);
    rs = rsqrtf(var + EPS);
    float r = fmaxf(d * rs * g2[lane] + be2[lane], 0.f);
    float v = warp_sum(r * w3[lane]);
    if (lane == 0) out[b] = v + b3[0];
}

// ---------------- launch ----------------
// Order puts k_edge(l=0) at launch position 3 — the slot the ncu capture
// empirically grabbed last round (it caught k_wconst, which sat there).
// deg/zero are only needed by k_update, so they legally move after edge0.
extern "C" void kernel_launch(void* const* d_in, const int* in_sizes, int n_in,
                              void* d_out, int out_size) {
    const float* x       = (const float*)d_in[0];
    const float* eattr   = (const float*)d_in[1];
    const float* ne_w1   = (const float*)d_in[2];
    const float* ne_b1   = (const float*)d_in[3];
    const float* ne_g1   = (const float*)d_in[4];
    const float* ne_be1  = (const float*)d_in[5];
    const float* ne_w2   = (const float*)d_in[6];
    const float* ne_b2   = (const float*)d_in[7];
    const float* ne_g2   = (const float*)d_in[8];
    const float* ne_be2  = (const float*)d_in[9];
    const float* conv_w  = (const float*)d_in[10];
    const float* conv_b  = (const float*)d_in[11];
    const float* conv_mg = (const float*)d_in[12];
    const float* conv_mb = (const float*)d_in[13];
    const float* conv_ng = (const float*)d_in[14];
    const float* conv_nb = (const float*)d_in[15];
    const float* out_ng  = (const float*)d_in[16];
    const float* out_nb  = (const float*)d_in[17];
    const float* m_w1    = (const float*)d_in[18];
    const float* m_b1    = (const float*)d_in[19];
    const float* m_g1    = (const float*)d_in[20];
    const float* m_be1   = (const float*)d_in[21];
    const float* m_w2    = (const float*)d_in[22];
    const float* m_b2    = (const float*)d_in[23];
    const float* m_g2    = (const float*)d_in[24];
    const float* m_be2   = (const float*)d_in[25];
    const float* m_w3    = (const float*)d_in[26];
    const float* m_b3    = (const float*)d_in[27];
    const int*   ei      = (const int*)d_in[28];
    const int*   batch   = (const int*)d_in[29];

    int N = in_sizes[0] / 2;
    int E = in_sizes[1] / 2;
    int B = out_size;

    int nblk = (N + 7) / 8;
    const int EDGE_BLOCKS = 148 * 8;

    int zero_work = N + B * H + B;
    int zblk = (zero_work + 255) / 256;
    if (zblk > 1184) zblk = 1184;

    k_embed<<<nblk, 256>>>(x, ne_w1, ne_b1, ne_g1, ne_be1,
                           ne_w2, ne_b2, ne_g2, ne_be2, N);          // 0
    k_wconst<<<1, 96>>>(conv_w);                                     // 1
    k_prep<<<nblk, 256>>>(conv_w, conv_b, 0, N);                     // 2
    k_edge<<<EDGE_BLOCKS, 256>>>(ei, eattr, conv_w,
                                 conv_mg, conv_mb, 0, E);            // 3 <- capture slot
    k_zero<<<zblk, 256>>>(N, B);                                     // 4
    k_deg<<<EDGE_BLOCKS, 256>>>(ei, E);                              // 5
    k_update<<<nblk, 256>>>(conv_ng, conv_nb, out_ng, out_nb,
                            batch, 0, N, 0);                         // 6
    for (int l = 1; l < 3; l++) {
        k_prep<<<nblk, 256>>>(conv_w, conv_b, l, N);
        k_edge<<<EDGE_BLOCKS, 256>>>(ei, eattr, conv_w, conv_mg, conv_mb, l, E);
        k_update<<<nblk, 256>>>(conv_ng, conv_nb, out_ng, out_nb,
                                batch, l, N, l == 2 ? 1 : 0);
    }
    k_head<<<(B + 7) / 8, 256>>>(m_w1, m_b1, m_g1, m_be1,
                                 m_w2, m_b2, m_g2, m_be2,
                                 m_w3, m_b3, (float*)d_out, B);
}